// round 8
// baseline (speedup 1.0000x reference)
#include <cuda_runtime.h>

#define BB 8
#define NN 16384
#define DD 768
#define CC 8
#define NCLS 2
#define D4 (DD/4)               // 192 float4 per row
#define BPB 37                  // blocks per bag
#define NBLK (BB*BPB)           // 296 = 2 * 148 SMs, exactly one wave
#define NSEG (BB*CC)            // 64
#define BTH 768
#define GROUPS 8
#define GTH 96                  // threads per group; thread owns cols (c, c+96)
#define RBASE (NN/BPB)          // 442
#define REXTRA (NN - RBASE*BPB) // 30 blocks get 443
#define RMAX 448
#define NW 14                   // warps covering RMAX rows

// Scratch (device globals — allocation-free per harness rules)
__device__ float g_partials[NBLK * CC * DD];   // 7.3 MB
__device__ int   g_cntp[NBLK * CC];
__device__ float g_logits[NSEG * NCLS];
__device__ int   g_done;                        // completion counter (self-resetting)

__global__ __launch_bounds__(BTH, 2)
void seg_sum_kernel(const float* __restrict__ inst, const int* __restrict__ labels) {
    // s_acc first and explicitly 16B-aligned: it is accessed as float4.
    __shared__ __align__(16) float s_acc[CC * DD];   // 24 KB
    __shared__ int   s_sorted[RMAX];
    __shared__ int   s_hist[NW][CC];
    __shared__ int   s_off[CC + 1];
    __shared__ int   s_cnt[CC];

    const int t   = threadIdx.x;
    const int bag = blockIdx.x / BPB;
    const int bi  = blockIdx.x % BPB;
    const int rstart = bi * RBASE + (bi < REXTRA ? bi : REXTRA);
    const int R      = RBASE + (bi < REXTRA ? 1 : 0);       // 442 or 443

    // ---- zero ----
    if (t < NW * CC) ((int*)s_hist)[t] = 0;
    for (int i = t; i < CC * DD; i += BTH) s_acc[i] = 0.0f;
    __syncthreads();

    // ---- deterministic counting sort of row indices by label ----
    int mylbl = -1, mypos = 0, myw = t >> 5;
    if (t < NW * 32) {
        mylbl = (t < R) ? labels[(long)bag * NN + rstart + t] : -1;
        unsigned mask = __match_any_sync(0xffffffffu, mylbl);
        int lane = t & 31;
        mypos = __popc(mask & ((1u << lane) - 1u));
        if (mylbl >= 0 && lane == (__ffs(mask) - 1))
            s_hist[myw][mylbl] = __popc(mask);
    }
    __syncthreads();
    if (t == 0) {
        int run = 0;
        #pragma unroll
        for (int l = 0; l < CC; ++l) {
            int c = 0;
            #pragma unroll
            for (int w = 0; w < NW; ++w) c += s_hist[w][l];
            s_cnt[l] = c;
            s_off[l] = run;
            run += c;
        }
        s_off[CC] = run;
    }
    __syncthreads();
    if (mylbl >= 0) {
        int base = s_off[mylbl];
        #pragma unroll
        for (int w = 0; w < NW; ++w)
            if (w < myw) base += s_hist[w][mylbl];
        s_sorted[base + mypos] = t;             // local row index
    }
    __syncthreads();

    // ---- hot loop: each group walks a contiguous slice of the sorted list ----
    const int g   = t / GTH;
    const int col = t % GTH;
    const int p0  = (R * g) / GROUPS;
    const int p1  = (R * (g + 1)) / GROUPS;

    const float4* __restrict__ base4 =
        reinterpret_cast<const float4*>(inst) + ((long)bag * NN + rstart) * D4;

    #pragma unroll
    for (int l = 0; l < CC; ++l) {
        int s = s_off[l]     > p0 ? s_off[l]     : p0;
        int e = s_off[l + 1] < p1 ? s_off[l + 1] : p1;
        if (s >= e) continue;

        float4 a0 = make_float4(0.f, 0.f, 0.f, 0.f);
        float4 a1 = make_float4(0.f, 0.f, 0.f, 0.f);
        int j = s;
        for (; j + 2 <= e; j += 2) {            // 4 LDG.128 in flight / thread
            int r0 = s_sorted[j];
            int r1 = s_sorted[j + 1];
            float4 v0 = __ldcs(&base4[(long)r0 * D4 + col]);
            float4 w0 = __ldcs(&base4[(long)r0 * D4 + col + GTH]);
            float4 v1 = __ldcs(&base4[(long)r1 * D4 + col]);
            float4 w1 = __ldcs(&base4[(long)r1 * D4 + col + GTH]);
            a0.x += v0.x; a0.y += v0.y; a0.z += v0.z; a0.w += v0.w;
            a1.x += w0.x; a1.y += w0.y; a1.z += w0.z; a1.w += w0.w;
            a0.x += v1.x; a0.y += v1.y; a0.z += v1.z; a0.w += v1.w;
            a1.x += w1.x; a1.y += w1.y; a1.z += w1.z; a1.w += w1.w;
        }
        if (j < e) {
            int r = s_sorted[j];
            float4 v = __ldcs(&base4[(long)r * D4 + col]);
            float4 w = __ldcs(&base4[(long)r * D4 + col + GTH]);
            a0.x += v.x; a0.y += v.y; a0.z += v.z; a0.w += v.w;
            a1.x += w.x; a1.y += w.y; a1.z += w.z; a1.w += w.w;
        }
        // flush run-partial (<= ~8 flushes per thread total)
        float* d0 = &s_acc[l * DD + col * 4];
        float* d1 = &s_acc[l * DD + (col + GTH) * 4];
        atomicAdd(d0 + 0, a0.x); atomicAdd(d0 + 1, a0.y);
        atomicAdd(d0 + 2, a0.z); atomicAdd(d0 + 3, a0.w);
        atomicAdd(d1 + 0, a1.x); atomicAdd(d1 + 1, a1.y);
        atomicAdd(d1 + 2, a1.z); atomicAdd(d1 + 3, a1.w);
    }
    __syncthreads();

    // ---- write block partials (plain stores) ----
    float4* part = reinterpret_cast<float4*>(g_partials) + (long)blockIdx.x * CC * D4;
    const float4* sa = reinterpret_cast<const float4*>(s_acc);
    for (int i = t; i < CC * D4; i += BTH) part[i] = sa[i];
    if (t < CC) g_cntp[blockIdx.x * CC + t] = s_cnt[t];
}

// One block per segment: reduce 37 partials + dot with head_w.
// The LAST block to finish also performs softmax/argmax/gather -> out.
__global__ __launch_bounds__(D4)
void reduce_head_kernel(const float* __restrict__ head_w,
                        const float* __restrict__ head_b,
                        float* __restrict__ out) {
    const int seg = blockIdx.x;
    const int bag = seg / CC, c = seg % CC;
    const int t = threadIdx.x;              // one float4 column
    const int lane = t & 31, w = t >> 5;    // 6 warps

    __shared__ float s_part[D4 / 32][2];
    __shared__ int   s_c[BPB];
    __shared__ int   s_last;

    if (t < BPB) s_c[t] = g_cntp[(bag * BPB + t) * CC + c];

    const float4* src = reinterpret_cast<const float4*>(g_partials)
                        + ((long)(bag * BPB) * CC + c) * D4 + t;
    float4 acc = make_float4(0.f, 0.f, 0.f, 0.f);
    #pragma unroll 4
    for (int k = 0; k < BPB; ++k) {
        float4 v = src[(long)k * CC * D4];
        acc.x += v.x; acc.y += v.y; acc.z += v.z; acc.w += v.w;
    }

    float4 w0 = reinterpret_cast<const float4*>(head_w)[t];
    float4 w1 = reinterpret_cast<const float4*>(head_w)[D4 + t];
    float l0 = acc.x * w0.x + acc.y * w0.y + acc.z * w0.z + acc.w * w0.w;
    float l1 = acc.x * w1.x + acc.y * w1.y + acc.z * w1.z + acc.w * w1.w;
    #pragma unroll
    for (int o = 16; o > 0; o >>= 1) {
        l0 += __shfl_xor_sync(0xffffffff, l0, o);
        l1 += __shfl_xor_sync(0xffffffff, l1, o);
    }
    if (lane == 0) { s_part[w][0] = l0; s_part[w][1] = l1; }
    __syncthreads();

    if (t == 0) {
        float L0 = 0.f, L1 = 0.f;
        #pragma unroll
        for (int i = 0; i < D4 / 32; ++i) { L0 += s_part[i][0]; L1 += s_part[i][1]; }
        int cnt = 0;
        #pragma unroll
        for (int k = 0; k < BPB; ++k) cnt += s_c[k];
        float inv = 1.0f / (float)(cnt > 0 ? cnt : 1);
        g_logits[seg * NCLS + 0] = L0 * inv + head_b[0];
        g_logits[seg * NCLS + 1] = L1 * inv + head_b[1];
        __threadfence();                          // publish logits
        int old = atomicAdd(&g_done, 1);
        s_last = (old == NSEG - 1) ? 1 : 0;
    }
    __syncthreads();

    if (s_last) {
        if (t < BB) {                             // finalize: one thread per bag
            float best = -1e30f, bl0 = 0.f, bl1 = 0.f;
            #pragma unroll
            for (int cc = 0; cc < CC; ++cc) {
                float l0v = __ldcg(&g_logits[(t * CC + cc) * NCLS + 0]);
                float l1v = __ldcg(&g_logits[(t * CC + cc) * NCLS + 1]);
                float m  = fmaxf(l0v, l1v);
                float e0 = expf(l0v - m), e1 = expf(l1v - m);
                float score = 1.0f - e0 / (e0 + e1);   // 1 - p[nor_index=0]
                if (score > best) { best = score; bl0 = l0v; bl1 = l1v; }
            }
            out[t * NCLS + 0] = bl0;
            out[t * NCLS + 1] = bl1;
        }
        __syncthreads();
        if (t == 0) g_done = 0;                   // reset for next graph replay
    }
}

extern "C" void kernel_launch(void* const* d_in, const int* in_sizes, int n_in,
                              void* d_out, int out_size) {
    const float* inst_feat = (const float*)d_in[0];   // [B, N, D] f32
    const int*   labels    = (const int*)  d_in[1];   // [B, N] i32
    const float* head_w    = (const float*)d_in[2];   // [NC, D] f32
    const float* head_b    = (const float*)d_in[3];   // [NC] f32
    float* out = (float*)d_out;                       // [B, NC] f32

    seg_sum_kernel<<<NBLK, BTH>>>(inst_feat, labels);
    reduce_head_kernel<<<NSEG, D4>>>(head_w, head_b, out);
}

// round 9
// speedup vs baseline: 1.0276x; 1.0276x over previous
#include <cuda_runtime.h>

#define BB 8
#define NN 16384
#define DD 768
#define CC 8
#define NCLS 2
#define D4 (DD/4)               // 192 float4 per row
#define BPB 37                  // blocks per bag
#define NBLK (BB*BPB)           // 296 = 2 * 148 SMs, exactly one wave
#define NSEG (BB*CC)            // 64
#define BTH 768
#define GROUPS 8
#define GTH 96                  // threads per group; thread owns cols (c, c+96)
#define RBASE (NN/BPB)          // 442
#define REXTRA (NN - RBASE*BPB) // 30 blocks get 443
#define RMAX 448
#define NW 14                   // warps covering RMAX rows
#define KQ 4                    // k-split in reduce_head

// Scratch (device globals — allocation-free per harness rules)
__device__ float g_partials[NBLK * CC * DD];   // 7.3 MB
__device__ int   g_cntp[NBLK * CC];
__device__ float g_logits[NSEG * NCLS];

__global__ __launch_bounds__(BTH, 2)
void seg_sum_kernel(const float* __restrict__ inst, const int* __restrict__ labels) {
    // s_acc first and explicitly 16B-aligned: it is accessed as float4.
    __shared__ __align__(16) float s_acc[CC * DD];   // 24 KB
    __shared__ int   s_sorted[RMAX];
    __shared__ int   s_hist[NW][CC];
    __shared__ int   s_off[CC + 1];
    __shared__ int   s_cnt[CC];

    const int t   = threadIdx.x;
    const int bag = blockIdx.x / BPB;
    const int bi  = blockIdx.x % BPB;
    const int rstart = bi * RBASE + (bi < REXTRA ? bi : REXTRA);
    const int R      = RBASE + (bi < REXTRA ? 1 : 0);       // 442 or 443

    // ---- zero ----
    if (t < NW * CC) ((int*)s_hist)[t] = 0;
    for (int i = t; i < CC * DD; i += BTH) s_acc[i] = 0.0f;
    __syncthreads();

    // ---- deterministic counting sort of row indices by label ----
    int mylbl = -1, mypos = 0, myw = t >> 5;
    if (t < NW * 32) {
        mylbl = (t < R) ? labels[(long)bag * NN + rstart + t] : -1;
        unsigned mask = __match_any_sync(0xffffffffu, mylbl);
        int lane = t & 31;
        mypos = __popc(mask & ((1u << lane) - 1u));
        if (mylbl >= 0 && lane == (__ffs(mask) - 1))
            s_hist[myw][mylbl] = __popc(mask);
    }
    __syncthreads();
    if (t == 0) {
        int run = 0;
        #pragma unroll
        for (int l = 0; l < CC; ++l) {
            int c = 0;
            #pragma unroll
            for (int w = 0; w < NW; ++w) c += s_hist[w][l];
            s_cnt[l] = c;
            s_off[l] = run;
            run += c;
        }
        s_off[CC] = run;
    }
    __syncthreads();
    if (mylbl >= 0) {
        int base = s_off[mylbl];
        #pragma unroll
        for (int w = 0; w < NW; ++w)
            if (w < myw) base += s_hist[w][mylbl];
        s_sorted[base + mypos] = t;             // local row index
    }
    __syncthreads();

    // ---- hot loop: each group walks a contiguous slice of the sorted list ----
    const int g   = t / GTH;
    const int col = t % GTH;
    const int p0  = (R * g) / GROUPS;
    const int p1  = (R * (g + 1)) / GROUPS;

    const float4* __restrict__ base4 =
        reinterpret_cast<const float4*>(inst) + ((long)bag * NN + rstart) * D4;

    #pragma unroll
    for (int l = 0; l < CC; ++l) {
        int s = s_off[l]     > p0 ? s_off[l]     : p0;
        int e = s_off[l + 1] < p1 ? s_off[l + 1] : p1;
        if (s >= e) continue;

        float4 a0 = make_float4(0.f, 0.f, 0.f, 0.f);
        float4 a1 = make_float4(0.f, 0.f, 0.f, 0.f);
        int j = s;
        for (; j + 2 <= e; j += 2) {            // 4 LDG.128 in flight / thread
            int r0 = s_sorted[j];
            int r1 = s_sorted[j + 1];
            float4 v0 = __ldcs(&base4[(long)r0 * D4 + col]);
            float4 w0 = __ldcs(&base4[(long)r0 * D4 + col + GTH]);
            float4 v1 = __ldcs(&base4[(long)r1 * D4 + col]);
            float4 w1 = __ldcs(&base4[(long)r1 * D4 + col + GTH]);
            a0.x += v0.x; a0.y += v0.y; a0.z += v0.z; a0.w += v0.w;
            a1.x += w0.x; a1.y += w0.y; a1.z += w0.z; a1.w += w0.w;
            a0.x += v1.x; a0.y += v1.y; a0.z += v1.z; a0.w += v1.w;
            a1.x += w1.x; a1.y += w1.y; a1.z += w1.z; a1.w += w1.w;
        }
        if (j < e) {
            int r = s_sorted[j];
            float4 v = __ldcs(&base4[(long)r * D4 + col]);
            float4 w = __ldcs(&base4[(long)r * D4 + col + GTH]);
            a0.x += v.x; a0.y += v.y; a0.z += v.z; a0.w += v.w;
            a1.x += w.x; a1.y += w.y; a1.z += w.z; a1.w += w.w;
        }
        // flush run-partial (<= ~8 flushes per thread total)
        float* d0 = &s_acc[l * DD + col * 4];
        float* d1 = &s_acc[l * DD + (col + GTH) * 4];
        atomicAdd(d0 + 0, a0.x); atomicAdd(d0 + 1, a0.y);
        atomicAdd(d0 + 2, a0.z); atomicAdd(d0 + 3, a0.w);
        atomicAdd(d1 + 0, a1.x); atomicAdd(d1 + 1, a1.y);
        atomicAdd(d1 + 2, a1.z); atomicAdd(d1 + 3, a1.w);
    }
    __syncthreads();

    // ---- write block partials (plain stores) ----
    float4* part = reinterpret_cast<float4*>(g_partials) + (long)blockIdx.x * CC * D4;
    const float4* sa = reinterpret_cast<const float4*>(s_acc);
    for (int i = t; i < CC * D4; i += BTH) part[i] = sa[i];
    if (t < CC) g_cntp[blockIdx.x * CC + t] = s_cnt[t];
}

// One block per segment, 768 threads: 4-way k-split over 37 partials,
// then dot with head_w. L2-latency-optimized (4x MLP vs single-split).
__global__ __launch_bounds__(KQ * D4)
void reduce_head_kernel(const float* __restrict__ head_w,
                        const float* __restrict__ head_b) {
    const int seg = blockIdx.x;
    const int bag = seg / CC, c = seg % CC;
    const int t   = threadIdx.x;
    const int col = t % D4;                 // float4 column
    const int q   = t / D4;                 // k-quarter 0..3

    __shared__ __align__(16) float4 s_q[KQ][D4];
    __shared__ float s_part[D4 / 32][2];
    __shared__ int   s_c[BPB];

    if (t < BPB) s_c[t] = g_cntp[(bag * BPB + t) * CC + c];

    // quarter q reduces partials [k0, k1)
    const int k0 = (BPB * q) / KQ;
    const int k1 = (BPB * (q + 1)) / KQ;
    const float4* src = reinterpret_cast<const float4*>(g_partials)
                        + ((long)(bag * BPB) * CC + c) * D4 + col;
    float4 acc = make_float4(0.f, 0.f, 0.f, 0.f);
    #pragma unroll 5
    for (int k = k0; k < k1; ++k) {
        float4 v = src[(long)k * CC * D4];
        acc.x += v.x; acc.y += v.y; acc.z += v.z; acc.w += v.w;
    }
    s_q[q][col] = acc;
    __syncthreads();

    if (t < D4) {
        float4 a0 = s_q[0][col], a1 = s_q[1][col], a2 = s_q[2][col], a3 = s_q[3][col];
        acc.x = (a0.x + a1.x) + (a2.x + a3.x);
        acc.y = (a0.y + a1.y) + (a2.y + a3.y);
        acc.z = (a0.z + a1.z) + (a2.z + a3.z);
        acc.w = (a0.w + a1.w) + (a2.w + a3.w);

        float4 w0 = reinterpret_cast<const float4*>(head_w)[col];
        float4 w1 = reinterpret_cast<const float4*>(head_w)[D4 + col];
        float l0 = acc.x * w0.x + acc.y * w0.y + acc.z * w0.z + acc.w * w0.w;
        float l1 = acc.x * w1.x + acc.y * w1.y + acc.z * w1.z + acc.w * w1.w;
        #pragma unroll
        for (int o = 16; o > 0; o >>= 1) {
            l0 += __shfl_xor_sync(0xffffffff, l0, o);
            l1 += __shfl_xor_sync(0xffffffff, l1, o);
        }
        if ((t & 31) == 0) { s_part[t >> 5][0] = l0; s_part[t >> 5][1] = l1; }
    }
    __syncthreads();

    if (t == 0) {
        float L0 = 0.f, L1 = 0.f;
        #pragma unroll
        for (int i = 0; i < D4 / 32; ++i) { L0 += s_part[i][0]; L1 += s_part[i][1]; }
        int cnt = 0;
        #pragma unroll
        for (int k = 0; k < BPB; ++k) cnt += s_c[k];
        float inv = 1.0f / (float)(cnt > 0 ? cnt : 1);
        g_logits[seg * NCLS + 0] = L0 * inv + head_b[0];
        g_logits[seg * NCLS + 1] = L1 * inv + head_b[1];
    }
}

__global__ void final_kernel(float* __restrict__ out) {
    int t = threadIdx.x;
    if (t < BB) {
        float best = -1e30f, bl0 = 0.f, bl1 = 0.f;
        #pragma unroll
        for (int c = 0; c < CC; ++c) {
            float l0 = g_logits[(t * CC + c) * NCLS + 0];
            float l1 = g_logits[(t * CC + c) * NCLS + 1];
            float m  = fmaxf(l0, l1);
            float e0 = expf(l0 - m), e1 = expf(l1 - m);
            float score = 1.0f - e0 / (e0 + e1);       // 1 - p[nor_index=0]
            if (score > best) { best = score; bl0 = l0; bl1 = l1; }
        }
        out[t * NCLS + 0] = bl0;
        out[t * NCLS + 1] = bl1;
    }
}

extern "C" void kernel_launch(void* const* d_in, const int* in_sizes, int n_in,
                              void* d_out, int out_size) {
    const float* inst_feat = (const float*)d_in[0];   // [B, N, D] f32
    const int*   labels    = (const int*)  d_in[1];   // [B, N] i32
    const float* head_w    = (const float*)d_in[2];   // [NC, D] f32
    const float* head_b    = (const float*)d_in[3];   // [NC] f32
    float* out = (float*)d_out;                       // [B, NC] f32

    seg_sum_kernel<<<NBLK, BTH>>>(inst_feat, labels);
    reduce_head_kernel<<<NSEG, KQ * D4>>>(head_w, head_b);
    final_kernel<<<1, 32>>>(out);
}